// round 17
// baseline (speedup 1.0000x reference)
#include <cuda_runtime.h>

#define Ld 4096
#define Hd 512
#define Md 1024
#define G4H 2048
#define NCTA 128

// ---------------- scratch (device globals; no allocations allowed) ------------
__device__ float g_x0[Ld * Hd];          // x = embed + att@A
__device__ float g_scores[Ld * Md];      // raw scores
__device__ float g_pre[Ld * G4H];        // x @ W_ih^T + b_ih + b_hh
__device__ float g_pmax[32 * Md];        // per-block-row partial max
__device__ float g_psum[32 * Md];        // per-block-row partial sum
__device__ unsigned long long g_hpair[2][Hd];   // {tag(hi32), value bits(lo32)}

// ---------------- helpers ------------------------------------------------------
__device__ __forceinline__ unsigned long long ld_rlx_u64(const unsigned long long* p) {
    unsigned long long v;
    asm volatile("ld.relaxed.gpu.global.b64 %0, [%1];" : "=l"(v) : "l"(p) : "memory");
    return v;
}
__device__ __forceinline__ void st_rlx_u64(unsigned long long* p, unsigned long long v) {
    asm volatile("st.relaxed.gpu.global.b64 [%0], %1;" :: "l"(p), "l"(v) : "memory");
}
__device__ __forceinline__ float sigf(float x) { return 1.0f / (1.0f + __expf(-x)); }
__device__ __forceinline__ float tanh_acc(float x) {
    return fmaf(2.0f, 1.0f / (1.0f + __expf(-2.0f * x)), -1.0f);
}

#define BM 128
#define BN 128
#define BK 16

// ---------------- SGEMM (NT) + embed gather + per-block-row softmax stats -------
// scores[l,m] = embed[sent[l]] . A[m]; also inits g_hpair (4 row-blocks cover it).
__global__ __launch_bounds__(256) void gemm_nt_stats_embed_kernel(
    float* __restrict__ C, const int* __restrict__ sent,
    const float* __restrict__ embed, const float* __restrict__ B,
    int M, int N, int K)
{
    __shared__ float As[BK][BM + 4];
    __shared__ float Bs[BK][BN + 4];
    __shared__ int sent_s[BM];
    __shared__ float pm_s[16][128];
    __shared__ float ps_s[16][128];
    int tid = threadIdx.x;
    int bm = blockIdx.y * BM, bn = blockIdx.x * BN;
    int tx = tid & 15, ty = tid >> 4;

    if (blockIdx.x == 0 && blockIdx.y < 4)
        ((unsigned long long*)g_hpair)[blockIdx.y * 256 + tid] = 0ull;
    if (tid < BM) sent_s[tid] = sent[bm + tid];
    __syncthreads();

    float acc[8][8] = {};
    for (int kk = 0; kk < K; kk += BK) {
#pragma unroll
        for (int i = 0; i < 2; i++) {
            int idx = tid + i * 256;
            int row = idx >> 2, kc = (idx & 3) << 2;
            float4 v = *(const float4*)(embed + (size_t)sent_s[row] * K + kk + kc);
            As[kc + 0][row] = v.x; As[kc + 1][row] = v.y;
            As[kc + 2][row] = v.z; As[kc + 3][row] = v.w;
        }
#pragma unroll
        for (int i = 0; i < 2; i++) {
            int idx = tid + i * 256;
            int row = idx >> 2, kc = (idx & 3) << 2;
            float4 v = *(const float4*)(B + (size_t)(bn + row) * K + kk + kc);
            Bs[kc + 0][row] = v.x; Bs[kc + 1][row] = v.y;
            Bs[kc + 2][row] = v.z; Bs[kc + 3][row] = v.w;
        }
        __syncthreads();
#pragma unroll
        for (int k = 0; k < BK; k++) {
            float ar[8], br[8];
            *(float4*)(ar)     = *(const float4*)&As[k][ty * 8];
            *(float4*)(ar + 4) = *(const float4*)&As[k][ty * 8 + 4];
            *(float4*)(br)     = *(const float4*)&Bs[k][tx * 8];
            *(float4*)(br + 4) = *(const float4*)&Bs[k][tx * 8 + 4];
#pragma unroll
            for (int i = 0; i < 8; i++)
#pragma unroll
                for (int j = 0; j < 8; j++)
                    acc[i][j] = fmaf(ar[i], br[j], acc[i][j]);
        }
        __syncthreads();
    }
#pragma unroll
    for (int i = 0; i < 8; i++) {
        float* cp = C + (size_t)(bm + ty * 8 + i) * N + bn + tx * 8;
#pragma unroll
        for (int j = 0; j < 8; j++) cp[j] = acc[i][j];
    }
    // per-thread stats over its 8 rows, per column
#pragma unroll
    for (int j = 0; j < 8; j++) {
        float m = acc[0][j];
#pragma unroll
        for (int i = 1; i < 8; i++) m = fmaxf(m, acc[i][j]);
        float s = 0.f;
#pragma unroll
        for (int i = 0; i < 8; i++) s += __expf(acc[i][j] - m);
        pm_s[ty][tx * 8 + j] = m;
        ps_s[ty][tx * 8 + j] = s;
    }
    __syncthreads();
    if (tid < 128) {
        float mm = -3.4e38f;
#pragma unroll
        for (int k = 0; k < 16; k++) mm = fmaxf(mm, pm_s[k][tid]);
        float ss = 0.f;
#pragma unroll
        for (int k = 0; k < 16; k++) ss += ps_s[k][tid] * __expf(pm_s[k][tid] - mm);
        g_pmax[(size_t)blockIdx.y * Md + bn + tid] = mm;
        g_psum[(size_t)blockIdx.y * Md + bn + tid] = ss;
    }
}

// ---------------- SGEMM (NN) + fused softmax on A + embed addend -----------------
// x[l,n] = embed[sent[l],n] + sum_k softmax(scores)[l,k] * A[k,n]
__global__ __launch_bounds__(256) void gemm_nn_smax_embed_kernel(
    float* __restrict__ C, const float* __restrict__ A, const float* __restrict__ B,
    const int* __restrict__ sent, const float* __restrict__ embed,
    int M, int N, int K)
{
    __shared__ float As[BK][BM + 4];
    __shared__ float Bs[BK][BN + 4];
    __shared__ float cm_s[Md];
    __shared__ float cr_s[Md];
    __shared__ int sent_s[BM];
    int tid = threadIdx.x;
    int bm = blockIdx.y * BM, bn = blockIdx.x * BN;
    int tx = tid & 15, ty = tid >> 4;
    if (tid < BM) sent_s[tid] = sent[bm + tid];
    // combine partial column stats (32 row-blocks)
    for (int c = tid; c < Md; c += 256) {
        float mm = -3.4e38f;
#pragma unroll 8
        for (int b = 0; b < 32; b++) mm = fmaxf(mm, g_pmax[(size_t)b * Md + c]);
        float ss = 0.f;
#pragma unroll 8
        for (int b = 0; b < 32; b++)
            ss += g_psum[(size_t)b * Md + c] * __expf(g_pmax[(size_t)b * Md + c] - mm);
        cm_s[c] = mm;
        cr_s[c] = 1.0f / ss;
    }
    __syncthreads();

    float acc[8][8] = {};
    for (int kk = 0; kk < K; kk += BK) {
#pragma unroll
        for (int i = 0; i < 2; i++) {
            int idx = tid + i * 256;
            int row = idx >> 2, kc = (idx & 3) << 2;
            float4 v = *(const float4*)(A + (size_t)(bm + row) * K + kk + kc);
            As[kc + 0][row] = __expf(v.x - cm_s[kk + kc + 0]) * cr_s[kk + kc + 0];
            As[kc + 1][row] = __expf(v.y - cm_s[kk + kc + 1]) * cr_s[kk + kc + 1];
            As[kc + 2][row] = __expf(v.z - cm_s[kk + kc + 2]) * cr_s[kk + kc + 2];
            As[kc + 3][row] = __expf(v.w - cm_s[kk + kc + 3]) * cr_s[kk + kc + 3];
        }
#pragma unroll
        for (int i = 0; i < 2; i++) {
            int idx = tid + i * 256;
            int kr = idx >> 5, col = (idx & 31) << 2;
            float4 v = *(const float4*)(B + (size_t)(kk + kr) * N + bn + col);
            *(float4*)&Bs[kr][col] = v;
        }
        __syncthreads();
#pragma unroll
        for (int k = 0; k < BK; k++) {
            float ar[8], br[8];
            *(float4*)(ar)     = *(const float4*)&As[k][ty * 8];
            *(float4*)(ar + 4) = *(const float4*)&As[k][ty * 8 + 4];
            *(float4*)(br)     = *(const float4*)&Bs[k][tx * 8];
            *(float4*)(br + 4) = *(const float4*)&Bs[k][tx * 8 + 4];
#pragma unroll
            for (int i = 0; i < 8; i++)
#pragma unroll
                for (int j = 0; j < 8; j++)
                    acc[i][j] = fmaf(ar[i], br[j], acc[i][j]);
        }
        __syncthreads();
    }
#pragma unroll
    for (int i = 0; i < 8; i++) {
        float* cp = C + (size_t)(bm + ty * 8 + i) * N + bn + tx * 8;
        const float* ep = embed + (size_t)sent_s[ty * 8 + i] * N + bn + tx * 8;
#pragma unroll
        for (int j = 0; j < 8; j++) cp[j] = acc[i][j] + ep[j];
    }
}

// ---------------- tiled SGEMM (NT) with biases: pre = x @ W_ih^T + b1 + b2 ------
__global__ __launch_bounds__(256) void gemm_nt_bias_kernel(
    float* __restrict__ C, const float* __restrict__ A, const float* __restrict__ B,
    int M, int N, int K, const float* __restrict__ bias1, const float* __restrict__ bias2)
{
    __shared__ float As[BK][BM + 4];
    __shared__ float Bs[BK][BN + 4];
    int tid = threadIdx.x;
    int bm = blockIdx.y * BM, bn = blockIdx.x * BN;
    int tx = tid & 15, ty = tid >> 4;
    float acc[8][8] = {};
    for (int kk = 0; kk < K; kk += BK) {
#pragma unroll
        for (int i = 0; i < 2; i++) {
            int idx = tid + i * 256;
            int row = idx >> 2, kc = (idx & 3) << 2;
            float4 v = *(const float4*)(A + (size_t)(bm + row) * K + kk + kc);
            As[kc + 0][row] = v.x; As[kc + 1][row] = v.y;
            As[kc + 2][row] = v.z; As[kc + 3][row] = v.w;
        }
#pragma unroll
        for (int i = 0; i < 2; i++) {
            int idx = tid + i * 256;
            int row = idx >> 2, kc = (idx & 3) << 2;
            float4 v = *(const float4*)(B + (size_t)(bn + row) * K + kk + kc);
            Bs[kc + 0][row] = v.x; Bs[kc + 1][row] = v.y;
            Bs[kc + 2][row] = v.z; Bs[kc + 3][row] = v.w;
        }
        __syncthreads();
#pragma unroll
        for (int k = 0; k < BK; k++) {
            float ar[8], br[8];
            *(float4*)(ar)     = *(const float4*)&As[k][ty * 8];
            *(float4*)(ar + 4) = *(const float4*)&As[k][ty * 8 + 4];
            *(float4*)(br)     = *(const float4*)&Bs[k][tx * 8];
            *(float4*)(br + 4) = *(const float4*)&Bs[k][tx * 8 + 4];
#pragma unroll
            for (int i = 0; i < 8; i++)
#pragma unroll
                for (int j = 0; j < 8; j++)
                    acc[i][j] = fmaf(ar[i], br[j], acc[i][j]);
        }
        __syncthreads();
    }
    float bb[8];
#pragma unroll
    for (int j = 0; j < 8; j++)
        bb[j] = bias1[bn + tx * 8 + j] + bias2[bn + tx * 8 + j];
#pragma unroll
    for (int i = 0; i < 8; i++) {
        float* cp = C + (size_t)(bm + ty * 8 + i) * N + bn + tx * 8;
#pragma unroll
        for (int j = 0; j < 8; j++) cp[j] = acc[i][j] + bb[j];
    }
}

// ---------------- A -> A_new[0:1024] copy ---------------------------------------
__global__ __launch_bounds__(256) void copyA_kernel(const float* __restrict__ A,
                                                    float* __restrict__ dst) {
    size_t i = (size_t)blockIdx.x * blockDim.x + threadIdx.x;   // float4 index
    ((float4*)dst)[i] = ((const float4*)A)[i];
}

// ---------------- persistent LSTM scan (R16 champion + pipelined polls) ----------
// 128 CTAs x 256 threads. CTA b owns h indices [4b, 4b+4) -> 16 gate rows.
// Warp w computes gate rows 2w, 2w+1. Lane l owns h-slice [16l, 16l+16).
// Exchange: self-validating {value, step-tag} u64 words, RELAXED strong accesses
// (R15 win), g_pre prefetched one step ahead (R16 win). NEW: speculative
// double-issue polling — each retry issues the NEXT load pair before checking
// the current one, halving detect quantization (~270 -> ~135 cyc per round).
__global__ __launch_bounds__(256, 1) void lstm_kernel(
    const float* __restrict__ Whh, const float* __restrict__ h0,
    const float* __restrict__ c0, float* __restrict__ out_h,
    float* __restrict__ out_c, float* __restrict__ out_seq,
    float* __restrict__ out_anew_last)
{
    __shared__ float hs[Hd];
    __shared__ float gs[16];
    int bid = blockIdx.x, tid = threadIdx.x;
    int w = tid >> 5, l = tid & 31;
    int rl0 = 2 * w, rl1 = 2 * w + 1;
    int grow0 = (rl0 >> 2) * Hd + bid * 4 + (rl0 & 3);
    int grow1 = (rl1 >> 2) * Hd + bid * 4 + (rl1 & 3);

    float wr0[16], wr1[16];
    {
        const float4* p0 = (const float4*)(Whh + (size_t)grow0 * Hd + l * 16);
        const float4* p1 = (const float4*)(Whh + (size_t)grow1 * Hd + l * 16);
#pragma unroll
        for (int m = 0; m < 4; m++) {
            float4 v0 = p0[m], v1 = p1[m];
            wr0[4 * m + 0] = v0.x; wr0[4 * m + 1] = v0.y;
            wr0[4 * m + 2] = v0.z; wr0[4 * m + 3] = v0.w;
            wr1[4 * m + 0] = v1.x; wr1[4 * m + 1] = v1.y;
            wr1[4 * m + 2] = v1.z; wr1[4 * m + 3] = v1.w;
        }
    }
    hs[tid] = h0[tid];
    hs[tid + 256] = h0[tid + 256];
    float creg = (tid < 4) ? c0[bid * 4 + tid] : 0.f;

    // pre-activation pipeline register: load step 0's values before the loop
    float2 pre_cur = make_float2(0.f, 0.f);
    if (l == 0)
        pre_cur = __ldcg((const float2*)&g_pre[grow0]);
    __syncthreads();

    for (int t = 0; t < Ld; t++) {
        // dot products over the owned 16-slice (LDS.128, conflict-free)
        float a0 = 0.f, a1 = 0.f;
#pragma unroll
        for (int m = 0; m < 4; m++) {
            float4 h4 = *(const float4*)&hs[l * 16 + 4 * m];
            a0 = fmaf(wr0[4 * m + 0], h4.x, a0); a1 = fmaf(wr1[4 * m + 0], h4.x, a1);
            a0 = fmaf(wr0[4 * m + 1], h4.y, a0); a1 = fmaf(wr1[4 * m + 1], h4.y, a1);
            a0 = fmaf(wr0[4 * m + 2], h4.z, a0); a1 = fmaf(wr1[4 * m + 2], h4.z, a1);
            a0 = fmaf(wr0[4 * m + 3], h4.w, a0); a1 = fmaf(wr1[4 * m + 3], h4.w, a1);
        }
#pragma unroll
        for (int off = 16; off > 0; off >>= 1) {
            a0 += __shfl_down_sync(0xffffffffu, a0, off);
            a1 += __shfl_down_sync(0xffffffffu, a1, off);
        }
        if (l == 0) { gs[rl0] = a0 + pre_cur.x; gs[rl1] = a1 + pre_cur.y; }
        __syncthreads();

        int nb = (t + 1) & 1;
        unsigned tgt = (unsigned)(t + 1);

        if (tid < 4) {
            float iv = sigf(gs[tid]);
            float fv = sigf(gs[4 + tid]);
            float gv = tanh_acc(gs[8 + tid]);
            float ov = sigf(gs[12 + tid]);
            float cv = fmaf(fv, creg, iv * gv);
            creg = cv;
            float hv = ov * tanh_acc(cv);
            int hidx = bid * 4 + tid;
            unsigned long long pkt =
                ((unsigned long long)tgt << 32) | (unsigned long long)__float_as_uint(hv);
            st_rlx_u64(&g_hpair[nb][hidx], pkt);          // relaxed strong publish
            __stcg(&out_seq[(size_t)t * Hd + hidx], hv);
            if (t == Ld - 1) {
                out_h[hidx] = hv;
                out_c[hidx] = cv;
                out_anew_last[hidx] = hv;
            }
        }
        if (t == Ld - 1) break;

        // prefetch next step's pre-activations in the wait window (lane0/warp)
        if (l == 0)
            pre_cur = __ldcg((const float2*)&g_pre[(size_t)(t + 1) * G4H + grow0]);

        // pipelined poll: issue next load pair before checking the current one
        {
            const unsigned long long* p0 = &g_hpair[nb][tid];
            const unsigned long long* p1 = &g_hpair[nb][tid + 256];
            unsigned long long v0 = ld_rlx_u64(p0);
            unsigned long long v1 = ld_rlx_u64(p1);
            for (;;) {
                unsigned long long n0 = ld_rlx_u64(p0);   // speculative next round
                unsigned long long n1 = ld_rlx_u64(p1);
                bool ok0 = (unsigned)(v0 >> 32) >= tgt;
                bool ok1 = (unsigned)(v1 >> 32) >= tgt;
                if (ok0 && ok1) break;
                if (ok0) n0 = v0;                          // keep validated value
                if (ok1) n1 = v1;
                v0 = n0; v1 = n1;
            }
            hs[tid]       = __uint_as_float((unsigned)v0);
            hs[tid + 256] = __uint_as_float((unsigned)v1);
        }
        __syncthreads();
    }
}

// ---------------- launch ---------------------------------------------------------
extern "C" void kernel_launch(void* const* d_in, const int* in_sizes, int n_in,
                              void* d_out, int out_size) {
    const int*   sent  = (const int*)d_in[0];
    const float* h0    = (const float*)d_in[1];
    const float* c0    = (const float*)d_in[2];
    const float* A     = (const float*)d_in[3];
    const float* embed = (const float*)d_in[4];
    const float* W_ih  = (const float*)d_in[5];
    const float* W_hh  = (const float*)d_in[6];
    const float* b_ih  = (const float*)d_in[7];
    const float* b_hh  = (const float*)d_in[8];

    float* out = (float*)d_out;
    float* out_h = out;
    float* out_c = out + Hd;
    float* out_seq = out + 2 * Hd;
    float* out_anew = out + 2 * Hd + (size_t)Ld * Hd;
    float* out_anew_last = out_anew + (size_t)Md * Hd;

    float* d_x0; float* d_scores; float* d_pre;
    cudaGetSymbolAddress((void**)&d_x0, g_x0);
    cudaGetSymbolAddress((void**)&d_scores, g_scores);
    cudaGetSymbolAddress((void**)&d_pre, g_pre);

    // launch 0: scores = embed[sent] @ A^T (+ block-row softmax stats, + g_hpair init)
    gemm_nt_stats_embed_kernel<<<dim3(Md / BN, Ld / BM), 256>>>(
        d_scores, sent, embed, A, Ld, Md, Hd);
    // launch 1: x = embed[sent] + softmax(scores) @ A (stats combined in-kernel)
    gemm_nn_smax_embed_kernel<<<dim3(Hd / BN, Ld / BM), 256>>>(
        d_x0, d_scores, A, sent, embed, Ld, Hd, Md);
    // launch 2: pre = x @ W_ih^T + b_ih + b_hh
    gemm_nt_bias_kernel<<<dim3(G4H / BN, Ld / BM), 256>>>(
        d_pre, d_x0, W_ih, Ld, G4H, Hd, b_ih, b_hh);
    // launch 3: LSTM scan (persistent, 128 CTAs)
    lstm_kernel<<<NCTA, 256>>>(W_hh, h0, c0, out_h, out_c, out_seq, out_anew_last);
    // launch 4: A_new rows 0..1023
    copyA_kernel<<<(Md * Hd / 4) / 256, 256>>>(A, out_anew);
}